// round 2
// baseline (speedup 1.0000x reference)
#include <cuda_runtime.h>
#include <cstdint>

#define NQ    32
#define KCB   1024
#define CDIM  8
#define DDIM  1024
#define BDIMS 8
#define TDIM  4096
#define TILE  32
#define NTH   256
#define NCOLS (BDIMS*TDIM)          /* 32768 */
#define BDT   (BDIMS*DDIM*TDIM)     /* 33554432 */
#define NQBT  (NQ*NCOLS)            /* 1048576 */

#define CBTS  1032                  /* cbT row stride (floats) */

/* shared memory offsets (floats) */
#define SM_IW   0                   /* iw dup'd: 1024 x 8 x float2 = 16384 */
#define SM_OW   16384               /* ow dup'd: 16384 */
#define SM_OB   32768               /* ob dup'd: 1024 x float2 = 2048 */
#define SM_CBT  34816               /* cb transposed: 8 x 1032 = 8256 */
#define SM_C2   43072               /* 1024 */
#define SM_ZE   44096               /* 32 x 9 = 288 */
#define SM_PART 44384               /* 8w x 16tp x 8c x float2 = 2048 */
#define SM_ZQ   46432               /* 16tp x 8c x float2 = 256 */
#define SM_M    46688               /* 32 */
#define SM_BD   46720               /* 256 */
#define SM_BK   46976               /* 256 */
#define SM_IB   47232               /* 8 */
#define SM_TOT  47240
#define SM_BYTES (SM_TOT*4)

typedef unsigned long long ull;

__device__ __forceinline__ ull f2x(float lo, float hi) {
    ull r;
    asm("mov.b64 %0, {%1, %2};" : "=l"(r)
        : "r"(__float_as_uint(lo)), "r"(__float_as_uint(hi)));
    return r;
}
__device__ __forceinline__ void upk(ull v, float& lo, float& hi) {
    unsigned a, b;
    asm("mov.b64 {%0, %1}, %2;" : "=r"(a), "=r"(b) : "l"(v));
    lo = __uint_as_float(a); hi = __uint_as_float(b);
}
#define FMA2(D,A,B,C) asm("fma.rn.f32x2 %0, %1, %2, %3;" : "=l"(D) : "l"(A), "l"(B), "l"(C))
#define ADD2(D,A,B)   asm("add.rn.f32x2 %0, %1, %2;"     : "=l"(D) : "l"(A), "l"(B))

__global__ __launch_bounds__(NTH, 1)
void rvq_kernel(const float* __restrict__ z,
                const float* __restrict__ iw,
                const float* __restrict__ ibias,
                const float* __restrict__ ow,
                const float* __restrict__ obias,
                const float* __restrict__ cb,
                const int*   __restrict__ inlen,
                float* __restrict__ out,
                int wout, int widx, int wlen)
{
    extern __shared__ float sm[];
    ull*   iwd  = (ull*)(sm + SM_IW);
    ull*   owd  = (ull*)(sm + SM_OW);
    ull*   obd  = (ull*)(sm + SM_OB);
    float* cbt  = sm + SM_CBT;
    float* c2_s = sm + SM_C2;
    float* ze_s = sm + SM_ZE;
    ull*   part = (ull*)(sm + SM_PART);
    ull*   zq_u = (ull*)(sm + SM_ZQ);
    float* zqf  = sm + SM_ZQ;
    float* m_s  = sm + SM_M;
    float* bd_s = sm + SM_BD;
    int*   bk_s = (int*)(sm + SM_BK);
    float* ib_s = sm + SM_IB;

    const int tid  = threadIdx.x;
    const int lane = tid & 31;
    const int w    = tid >> 5;          /* 0..7 */
    const int sub  = lane >> 4;         /* 0,1  */
    const int tp   = lane & 15;         /* t-pair 0..15 */
    const int d0   = w * 128 + sub * 64;

    const int col0 = blockIdx.x * TILE;
    const int b    = col0 >> 12;
    const int t0   = col0 & (TDIM - 1);
    const int len  = inlen[b];

    const float* zb = z + (size_t)b * DDIM * TDIM + t0 + 2 * tp;

    const float mlo = ((t0 + 2 * tp)     < len) ? 1.0f : 0.0f;
    const float mhi = ((t0 + 2 * tp + 1) < len) ? 1.0f : 0.0f;
    const ull nm2 = f2x(-mlo, -mhi);

    if (tid < 32) m_s[tid] = ((t0 + tid) < len) ? 1.0f : 0.0f;

    /* residual in registers: R[j] = packed {r(d0+j, t_lo), r(d0+j, t_hi)} */
    ull R[64];
    #pragma unroll
    for (int j = 0; j < 64; j++) {
        float2 v = *(const float2*)(zb + (size_t)(d0 + j) * TDIM);
        R[j] = f2x(v.x * mlo, v.y * mhi);
    }
    __syncthreads();

    for (int q = 0; q < NQ; q++) {
        /* ================= stage A: load & reshape params ================ */
        const float4* iw4 = (const float4*)(iw + q * (CDIM * DDIM));
        #pragma unroll
        for (int i = 0; i < 8; i++) {
            int idx = tid + i * 256;            /* 0..2047 */
            float4 v = iw4[idx];
            int c  = idx >> 8;                  /* 0..7 */
            int dd = (idx & 255) * 4;
            iwd[(dd + 0) * 8 + c] = f2x(v.x, v.x);
            iwd[(dd + 1) * 8 + c] = f2x(v.y, v.y);
            iwd[(dd + 2) * 8 + c] = f2x(v.z, v.z);
            iwd[(dd + 3) * 8 + c] = f2x(v.w, v.w);
        }
        const float4* ow4 = (const float4*)(ow + q * (DDIM * CDIM));
        #pragma unroll
        for (int i = 0; i < 8; i++) {
            int idx = tid + i * 256;
            float4 v = ow4[idx];
            int d  = idx >> 1;
            int c0 = (idx & 1) * 4;
            owd[d * 8 + c0 + 0] = f2x(v.x, v.x);
            owd[d * 8 + c0 + 1] = f2x(v.y, v.y);
            owd[d * 8 + c0 + 2] = f2x(v.z, v.z);
            owd[d * 8 + c0 + 3] = f2x(v.w, v.w);
        }
        {
            const float4* ob4 = (const float4*)(obias + q * DDIM);
            float4 v = ob4[tid];
            obd[tid * 4 + 0] = f2x(v.x, v.x);
            obd[tid * 4 + 1] = f2x(v.y, v.y);
            obd[tid * 4 + 2] = f2x(v.z, v.z);
            obd[tid * 4 + 3] = f2x(v.w, v.w);
        }
        const float4* cb4 = (const float4*)(cb + q * (KCB * CDIM));
        #pragma unroll
        for (int i = 0; i < 8; i++) {
            int idx = tid + i * 256;
            float4 v = cb4[idx];
            int k  = idx >> 1;
            int c0 = (idx & 1) * 4;
            cbt[(c0 + 0) * CBTS + k] = v.x;
            cbt[(c0 + 1) * CBTS + k] = v.y;
            cbt[(c0 + 2) * CBTS + k] = v.z;
            cbt[(c0 + 3) * CBTS + k] = v.w;
            float p = fmaf(v.x, v.x, fmaf(v.y, v.y, fmaf(v.z, v.z, v.w * v.w)));
            float o = __shfl_xor_sync(0xffffffffu, p, 1);
            if ((idx & 1) == 0) c2_s[k] = p + o;
        }
        if (tid < 8) ib_s[tid] = ibias[q * CDIM + tid];
        __syncthreads();

        /* ====== phase 1: z_e[c][t] = sum_d iw[c][d] * r[d][t]  (packed) === */
        {
            ull acc[8];
            #pragma unroll
            for (int c = 0; c < 8; c++) acc[c] = 0ull;
            #pragma unroll
            for (int j = 0; j < 64; j++) {
                const ulonglong2* wp = (const ulonglong2*)(iwd + (size_t)(d0 + j) * 8);
                ulonglong2 p0 = wp[0], p1 = wp[1], p2 = wp[2], p3 = wp[3];
                FMA2(acc[0], p0.x, R[j], acc[0]);
                FMA2(acc[1], p0.y, R[j], acc[1]);
                FMA2(acc[2], p1.x, R[j], acc[2]);
                FMA2(acc[3], p1.y, R[j], acc[3]);
                FMA2(acc[4], p2.x, R[j], acc[4]);
                FMA2(acc[5], p2.y, R[j], acc[5]);
                FMA2(acc[6], p3.x, R[j], acc[6]);
                FMA2(acc[7], p3.y, R[j], acc[7]);
            }
            /* combine the two 64-d halves within the warp */
            #pragma unroll
            for (int c = 0; c < 8; c++) {
                ull o = __shfl_xor_sync(0xffffffffu, acc[c], 16);
                ADD2(acc[c], acc[c], o);
            }
            if (sub == 0) {
                #pragma unroll
                for (int c = 0; c < 8; c++)
                    part[w * 128 + tp * 8 + c] = acc[c];
            }
        }
        __syncthreads();
        if (tid < 128) {                 /* final reduce over 8 warps */
            int c = tid & 7, tpp = tid >> 3;
            ull s = part[tpp * 8 + c];
            #pragma unroll
            for (int ww = 1; ww < 8; ww++) ADD2(s, s, part[ww * 128 + tpp * 8 + c]);
            float a, bv; upk(s, a, bv);
            float ib = ib_s[c];
            ze_s[(2 * tpp)     * 9 + c] = a  + ib;
            ze_s[(2 * tpp + 1) * 9 + c] = bv + ib;
        }
        __syncthreads();

        /* ====== phase 2: distances, argmin (k packed in pairs) =========== */
        {
            float e[8];
            #pragma unroll
            for (int c = 0; c < 8; c++) e[c] = ze_s[lane * 9 + c];
            float e2 = 0.f;
            #pragma unroll
            for (int c = 0; c < 8; c++) e2 = fmaf(e[c], e[c], e2);
            ull ed[8];
            #pragma unroll
            for (int c = 0; c < 8; c++) ed[c] = f2x(e[c], e[c]);
            const ull e2d = f2x(e2, e2);
            const ull n2  = f2x(-2.0f, -2.0f);

            float best = 3.402823466e38f;
            int bk = 0;
            const int kb = w << 7;
            #pragma unroll 8
            for (int i = 0; i < 32; i++) {
                int k = kb + i * 4;
                ull sA = 0ull, sB = 0ull;
                #pragma unroll
                for (int c = 0; c < 8; c++) {
                    ulonglong2 cv = *(const ulonglong2*)(cbt + c * CBTS + k);
                    FMA2(sA, cv.x, ed[c], sA);
                    FMA2(sB, cv.y, ed[c], sB);
                }
                ulonglong2 c2v = *(const ulonglong2*)(c2_s + k);
                ull bA, bB;
                ADD2(bA, c2v.x, e2d);
                ADD2(bB, c2v.y, e2d);
                FMA2(bA, sA, n2, bA);
                FMA2(bB, sB, n2, bB);
                float da, db, dc, dd;
                upk(bA, da, db); upk(bB, dc, dd);
                if (da < best) { best = da; bk = k;     }
                if (db < best) { best = db; bk = k + 1; }
                if (dc < best) { best = dc; bk = k + 2; }
                if (dd < best) { best = dd; bk = k + 3; }
            }
            bd_s[w * 32 + lane] = best;
            bk_s[w * 32 + lane] = bk;
        }
        __syncthreads();

        /* ====== final argmin across 8 k-chunks + stage -zq*m ============= */
        if (tid < 32) {
            int t = tid;
            float best = bd_s[t];
            int bk = bk_s[t];
            #pragma unroll
            for (int kc = 1; kc < 8; kc++) {
                float d2 = bd_s[kc * 32 + t];
                if (d2 < best) { best = d2; bk = bk_s[kc * 32 + t]; }
            }
            if (widx) out[BDT + q * NCOLS + col0 + t] = (float)bk;
            float m = m_s[t];
            int tpp = t >> 1, h = t & 1;
            #pragma unroll
            for (int c = 0; c < 8; c++)
                zqf[(tpp * 8 + c) * 2 + h] = -cbt[c * CBTS + bk] * m;
        }
        __syncthreads();

        /* ====== phase 3: r -= (ow . zq + ob) * m   (all in registers) ==== */
        {
            ull zq[8];
            #pragma unroll
            for (int c = 0; c < 8; c++) zq[c] = zq_u[tp * 8 + c];
            #pragma unroll
            for (int j = 0; j < 64; j++) {
                int d = d0 + j;
                const ulonglong2* wp = (const ulonglong2*)(owd + (size_t)d * 8);
                ulonglong2 p0 = wp[0], p1 = wp[1], p2 = wp[2], p3 = wp[3];
                ull a;
                FMA2(a, obd[d], nm2, R[j]);
                FMA2(a, p0.x, zq[0], a);
                FMA2(a, p0.y, zq[1], a);
                FMA2(a, p1.x, zq[2], a);
                FMA2(a, p1.y, zq[3], a);
                FMA2(a, p2.x, zq[4], a);
                FMA2(a, p2.y, zq[5], a);
                FMA2(a, p3.x, zq[6], a);
                FMA2(a, p3.y, zq[7], a);
                R[j] = a;
            }
        }
        __syncthreads();
    }

    /* ================= epilogue: qout = z*mask - r_final ================ */
    if (wout) {
        float* ob_ = out + (size_t)b * DDIM * TDIM + t0 + 2 * tp;
        #pragma unroll
        for (int j = 0; j < 64; j++) {
            int d = d0 + j;
            float2 zv = *(const float2*)(zb + (size_t)d * TDIM);
            float rl, rh; upk(R[j], rl, rh);
            float2 o;
            o.x = fmaf(zv.x, mlo, -rl);
            o.y = fmaf(zv.y, mhi, -rh);
            *(float2*)(ob_ + (size_t)d * TDIM) = o;
        }
    }
    if (wlen && blockIdx.x == 0 && tid < BDIMS)
        out[BDT + NQBT + tid] = (float)inlen[tid];
}

extern "C" void kernel_launch(void* const* d_in, const int* in_sizes, int n_in,
                              void* d_out, int out_size)
{
    const float* z   = (const float*)d_in[0];
    const float* iw  = (const float*)d_in[1];
    const float* ib  = (const float*)d_in[2];
    const float* ow  = (const float*)d_in[3];
    const float* ob  = (const float*)d_in[4];
    const float* cbk = (const float*)d_in[5];
    const int* inlen = (const int*)d_in[6];
    float* out = (float*)d_out;

    cudaFuncSetAttribute(rvq_kernel, cudaFuncAttributeMaxDynamicSharedMemorySize, SM_BYTES);

    int wout = (out_size >= BDT) ? 1 : 0;
    int widx = (out_size >= BDT + NQBT) ? 1 : 0;
    int wlen = (out_size >= BDT + NQBT + BDIMS) ? 1 : 0;

    rvq_kernel<<<NCOLS / TILE, NTH, SM_BYTES>>>(z, iw, ib, ow, ob, cbk, inlen,
                                               out, wout, widx, wlen);
}

// round 3
// speedup vs baseline: 1.3967x; 1.3967x over previous
#include <cuda_runtime.h>
#include <cstdint>

#define NQ    32
#define KCB   1024
#define CDIM  8
#define DDIM  1024
#define BDIMS 8
#define TDIM  4096
#define TILE  32
#define NTH   512
#define NCOLS (BDIMS*TDIM)          /* 32768 */
#define BDT   (BDIMS*DDIM*TDIM)     /* 33554432 */
#define NQBT  (NQ*NCOLS)            /* 1048576 */

/* shared memory offsets (floats) */
#define SM_R    0                   /* 1024 x 32 residual, swizzled float4 */
#define SM_W    32768               /* 8 x 1024 : iw (phase1) then owT (phase3) */
#define SM_OB   40960               /* 1024 */
#define SM_CB   41984               /* 1024 x 8 */
#define SM_C2   50176               /* 1024 */
#define SM_ZE   51200               /* 32 x 9 */
#define SM_PART 51488               /* 16 warps x 16 ull = 512 floats */
#define SM_ZQ   52000               /* 32 x 8 (negated * mask) */
#define SM_M    52256               /* 32 */
#define SM_BD   52288               /* 16 x 32 */
#define SM_BK   52800               /* 16 x 32 */
#define SM_IB   53312               /* 8 */
#define SM_TOT  53320
#define SM_BYTES (SM_TOT*4)

typedef unsigned long long ull;

__device__ float g_owT[NQ * CDIM * DDIM];   /* transposed out_w: [q][c][d] */
__device__ float g_c2[NQ * KCB];            /* |cb|^2 */

__device__ __forceinline__ ull f2x(float lo, float hi) {
    ull r;
    asm("mov.b64 %0, {%1, %2};" : "=l"(r)
        : "r"(__float_as_uint(lo)), "r"(__float_as_uint(hi)));
    return r;
}
#define ADD2(D,A,B) asm("add.rn.f32x2 %0, %1, %2;" : "=l"(D) : "l"(A), "l"(B))

__global__ void prep_kernel(const float* __restrict__ ow,
                            const float* __restrict__ cb)
{
    int idx = blockIdx.x * blockDim.x + threadIdx.x;
    int stride = gridDim.x * blockDim.x;
    for (int i = idx; i < NQ * CDIM * DDIM; i += stride) {
        int q = i >> 13, r = i & 8191, c = r >> 10, d = r & 1023;
        g_owT[i] = ow[(q << 13) + (d << 3) + c];
    }
    for (int k = idx; k < NQ * KCB; k += stride) {
        const float4* row = (const float4*)(cb + (size_t)k * 8);
        float4 a = row[0], b4 = row[1];
        float p = fmaf(a.x, a.x, fmaf(a.y, a.y, fmaf(a.z, a.z, a.w * a.w)));
        float o = fmaf(b4.x, b4.x, fmaf(b4.y, b4.y, fmaf(b4.z, b4.z, b4.w * b4.w)));
        g_c2[k] = p + o;
    }
}

__global__ __launch_bounds__(NTH, 1)
void rvq_kernel(const float* __restrict__ z,
                const float* __restrict__ iw,
                const float* __restrict__ ibias,
                const float* __restrict__ obias,
                const float* __restrict__ cb,
                const int*   __restrict__ inlen,
                float* __restrict__ out,
                int wout, int widx, int wlen)
{
    extern __shared__ float sm[];
    float* r_s   = sm + SM_R;
    float* w_s   = sm + SM_W;
    float* ob_s  = sm + SM_OB;
    float* cb_s  = sm + SM_CB;
    float* c2_s  = sm + SM_C2;
    float* ze_s  = sm + SM_ZE;
    ull*   partu = (ull*)(sm + SM_PART);
    float* partf = sm + SM_PART;
    float* zq_s  = sm + SM_ZQ;
    float* m_s   = sm + SM_M;
    float* bd_s  = sm + SM_BD;
    int*   bk_s  = (int*)(sm + SM_BK);
    float* ib_s  = sm + SM_IB;
    float4* R4   = (float4*)r_s;

    const int tid  = threadIdx.x;
    const int lane = tid & 31;
    const int w    = tid >> 5;          /* 0..15 */
    const int tg   = w >> 1;            /* t-group 0..7 (4 t's) */
    const int dg   = w & 1;             /* d-group 0..1 (512 d's) */
    const int dbase = dg * 512 + lane;

    const int col0 = blockIdx.x * TILE;
    const int b    = col0 >> 12;
    const int t0   = col0 & (TDIM - 1);
    const int len  = inlen[b];

    const float* zb = z + (size_t)b * DDIM * TDIM + t0;

    if (tid < TILE) m_s[tid] = ((t0 + tid) < len) ? 1.0f : 0.0f;

    /* ---- init residual = z * mask (swizzled float4 over t-quads) ---- */
    #pragma unroll
    for (int it = 0; it < 16; it++) {
        int i = tid + it * NTH;
        int d = i >> 3, tq = i & 7;
        float4 v = *(const float4*)(zb + (size_t)d * TDIM + (tq << 2));
        int tb = t0 + (tq << 2);
        v.x = (tb + 0 < len) ? v.x : 0.0f;
        v.y = (tb + 1 < len) ? v.y : 0.0f;
        v.z = (tb + 2 < len) ? v.z : 0.0f;
        v.w = (tb + 3 < len) ? v.w : 0.0f;
        R4[d * 8 + (tq ^ (d & 7))] = v;
    }
    __syncthreads();

    for (int q = 0; q < NQ; q++) {
        /* ---- stage A: iw -> w_s, cb -> cb_s, c2 -> c2_s (all clean copies) */
        {
            const float4* iw4 = (const float4*)(iw + (size_t)q * CDIM * DDIM);
            float4* w4 = (float4*)w_s;
            #pragma unroll
            for (int it = 0; it < 4; it++) w4[tid + it * NTH] = iw4[tid + it * NTH];

            const float4* cb4 = (const float4*)(cb + (size_t)q * KCB * CDIM);
            float4* cbs4 = (float4*)cb_s;
            #pragma unroll
            for (int it = 0; it < 4; it++) cbs4[tid + it * NTH] = cb4[tid + it * NTH];

            const float* c2g = g_c2 + q * KCB;
            #pragma unroll
            for (int it = 0; it < 2; it++) c2_s[tid + it * NTH] = c2g[tid + it * NTH];

            if (tid < 256) {
                ((float4*)ob_s)[tid] = ((const float4*)(obias + (size_t)q * DDIM))[tid];
            }
            if (tid < CDIM) ib_s[tid] = ibias[q * CDIM + tid];
        }
        __syncthreads();

        /* ---- phase 1: partial z_e over this warp's 512-d slice ---- */
        {
            float acc[8][4];
            #pragma unroll
            for (int c = 0; c < 8; c++)
                #pragma unroll
                for (int j = 0; j < 4; j++) acc[c][j] = 0.f;

            #pragma unroll 4
            for (int i = 0; i < 16; i++) {
                int d = dbase + (i << 5);
                float4 r4 = R4[d * 8 + (tg ^ (d & 7))];
                #pragma unroll
                for (int c = 0; c < 8; c++) {
                    float wv = w_s[c * 1024 + d];
                    acc[c][0] = fmaf(wv, r4.x, acc[c][0]);
                    acc[c][1] = fmaf(wv, r4.y, acc[c][1]);
                    acc[c][2] = fmaf(wv, r4.z, acc[c][2]);
                    acc[c][3] = fmaf(wv, r4.w, acc[c][3]);
                }
            }
            /* pack to f32x2 and shfl-reduce over 32 lanes */
            ull u[16];
            #pragma unroll
            for (int c = 0; c < 8; c++) {
                u[c * 2 + 0] = f2x(acc[c][0], acc[c][1]);
                u[c * 2 + 1] = f2x(acc[c][2], acc[c][3]);
            }
            #pragma unroll
            for (int off = 16; off > 0; off >>= 1)
                #pragma unroll
                for (int i = 0; i < 16; i++) {
                    ull o = __shfl_xor_sync(0xffffffffu, u[i], off);
                    ADD2(u[i], u[i], o);
                }
            if (lane == 0) {
                #pragma unroll
                for (int i = 0; i < 16; i++) partu[w * 16 + i] = u[i];
            }
        }
        __syncthreads();

        /* ---- combine partials -> ze_s ; stage B: owT -> w_s ---- */
        if (tid < 256) {
            int c = tid & 7, t = tid >> 3;
            int tgg = t >> 2, j = t & 3;
            float v = partf[(tgg * 2 + 0) * 32 + c * 4 + j]
                    + partf[(tgg * 2 + 1) * 32 + c * 4 + j]
                    + ib_s[c];
            ze_s[t * 9 + c] = v;
        }
        {
            const float4* owT4 = (const float4*)(g_owT + (size_t)q * CDIM * DDIM);
            float4* w4 = (float4*)w_s;
            #pragma unroll
            for (int it = 0; it < 4; it++) w4[tid + it * NTH] = owT4[tid + it * NTH];
        }
        __syncthreads();

        /* ---- phase 2: warp w scans k in [64w, 64w+64), lanes = t ---- */
        {
            int t = lane;
            float e[8];
            #pragma unroll
            for (int c = 0; c < 8; c++) e[c] = ze_s[t * 9 + c];

            float best = 3.402823466e38f;
            int bk = 0;
            const int kb = w << 6;
            #pragma unroll 4
            for (int i = 0; i < 64; i++) {
                int k = kb + i;          /* ascending -> first-min tie break */
                float4 cA = ((const float4*)cb_s)[k * 2];
                float4 cB = ((const float4*)cb_s)[k * 2 + 1];
                float s = 0.f;
                s = fmaf(cA.x, e[0], s); s = fmaf(cA.y, e[1], s);
                s = fmaf(cA.z, e[2], s); s = fmaf(cA.w, e[3], s);
                s = fmaf(cB.x, e[4], s); s = fmaf(cB.y, e[5], s);
                s = fmaf(cB.z, e[6], s); s = fmaf(cB.w, e[7], s);
                float dist = fmaf(-2.0f, s, c2_s[k]);  /* e2 dropped: rank-invariant */
                if (dist < best) { best = dist; bk = k; }
            }
            bd_s[w * 32 + t] = best;
            bk_s[w * 32 + t] = bk;
        }
        __syncthreads();

        /* ---- final argmin over 16 k-chunks + stage -zq*m ---- */
        if (tid < TILE) {
            int t = tid;
            float best = bd_s[t];
            int bk = bk_s[t];
            #pragma unroll
            for (int kc = 1; kc < 16; kc++) {  /* ascending kc = ascending k */
                float d2 = bd_s[kc * 32 + t];
                if (d2 < best) { best = d2; bk = bk_s[kc * 32 + t]; }
            }
            if (widx) out[BDT + q * NCOLS + col0 + t] = (float)bk;
            float m = m_s[t];
            #pragma unroll
            for (int c = 0; c < 8; c++)
                zq_s[t * 8 + c] = -cb_s[bk * 8 + c] * m;
        }
        __syncthreads();

        /* ---- phase 3: r[d][t] -= (owT[c][d].zq + ob[d]) * m ---- */
        {
            float zq[8][4], mj[4];
            #pragma unroll
            for (int j = 0; j < 4; j++) {
                int t = (tg << 2) + j;
                mj[j] = -m_s[t];
                #pragma unroll
                for (int c = 0; c < 8; c++) zq[c][j] = zq_s[t * 8 + c];
            }
            #pragma unroll 4
            for (int i = 0; i < 16; i++) {
                int d = dbase + (i << 5);
                int slot = d * 8 + (tg ^ (d & 7));
                float4 r4 = R4[slot];
                float obv = ob_s[d];
                float u0 = fmaf(obv, mj[0], r4.x);
                float u1 = fmaf(obv, mj[1], r4.y);
                float u2 = fmaf(obv, mj[2], r4.z);
                float u3 = fmaf(obv, mj[3], r4.w);
                #pragma unroll
                for (int c = 0; c < 8; c++) {
                    float wv = w_s[c * 1024 + d];
                    u0 = fmaf(wv, zq[c][0], u0);
                    u1 = fmaf(wv, zq[c][1], u1);
                    u2 = fmaf(wv, zq[c][2], u2);
                    u3 = fmaf(wv, zq[c][3], u3);
                }
                r4.x = u0; r4.y = u1; r4.z = u2; r4.w = u3;
                R4[slot] = r4;
            }
        }
        __syncthreads();
    }

    /* ---- epilogue: qout = z*mask - r_final ---- */
    if (wout) {
        #pragma unroll
        for (int it = 0; it < 16; it++) {
            int i = tid + it * NTH;
            int d = i >> 3, tq = i & 7;
            float4 zv = *(const float4*)(zb + (size_t)d * TDIM + (tq << 2));
            float4 rv = R4[d * 8 + (tq ^ (d & 7))];
            int tb = t0 + (tq << 2);
            float4 o;
            o.x = ((tb + 0 < len) ? zv.x : 0.0f) - rv.x;
            o.y = ((tb + 1 < len) ? zv.y : 0.0f) - rv.y;
            o.z = ((tb + 2 < len) ? zv.z : 0.0f) - rv.z;
            o.w = ((tb + 3 < len) ? zv.w : 0.0f) - rv.w;
            *(float4*)(out + (size_t)b * DDIM * TDIM + (size_t)d * TDIM + t0 + (tq << 2)) = o;
        }
    }
    if (wlen && blockIdx.x == 0 && tid < BDIMS)
        out[BDT + NQBT + tid] = (float)inlen[tid];
}

extern "C" void kernel_launch(void* const* d_in, const int* in_sizes, int n_in,
                              void* d_out, int out_size)
{
    const float* z   = (const float*)d_in[0];
    const float* iw  = (const float*)d_in[1];
    const float* ib  = (const float*)d_in[2];
    const float* ow  = (const float*)d_in[3];
    const float* ob  = (const float*)d_in[4];
    const float* cbk = (const float*)d_in[5];
    const int* inlen = (const int*)d_in[6];
    float* out = (float*)d_out;

    cudaFuncSetAttribute(rvq_kernel, cudaFuncAttributeMaxDynamicSharedMemorySize, SM_BYTES);

    int wout = (out_size >= BDT) ? 1 : 0;
    int widx = (out_size >= BDT + NQBT) ? 1 : 0;
    int wlen = (out_size >= BDT + NQBT + BDIMS) ? 1 : 0;

    prep_kernel<<<256, 512>>>(ow, cbk);
    rvq_kernel<<<NCOLS / TILE, NTH, SM_BYTES>>>(z, iw, ib, ob, cbk, inlen,
                                               out, wout, widx, wlen);
}